// round 4
// baseline (speedup 1.0000x reference)
#include <cuda_runtime.h>

// HybridQuanvolutionFraudNet: reference output = log_softmax(logits, axis=-1)
// with logits of shape [B, 1]. log_softmax over a size-1 axis is identically
// 0.0 (shifted = x - max = 0; logsumexp(0) = 0). All upstream computation
// (quanvolution 4-qubit statevector sim, tanh MLP, final linear) is dead.
// Output = zeros(out_size, float32). Verified: rel_err = 0.0 bitwise (R1, R3).
//
// R1: 2-block kernel          -> 4.58 µs (floor candidate; all pipes ~0%)
// R3: graph memset node       -> 5.50 µs REGRESSION (memset node dispatch
//     heavier than a kernel node on GB300 graph replay). Reverting.
// R4: single-CTA branchless kernel node — the cheapest possible graph node.

__global__ void zero_out_exact(float4* __restrict__ out) {
    // grid=1, block=512: 512 * 16B = 8192B = 2048 floats, exact fit.
    out[threadIdx.x] = make_float4(0.f, 0.f, 0.f, 0.f);
}

__global__ void zero_out_generic(float* __restrict__ out, int n) {
    int i = blockIdx.x * blockDim.x + threadIdx.x;
    if (i < n) out[i] = 0.f;
}

extern "C" void kernel_launch(void* const* d_in, const int* in_sizes, int n_in,
                              void* d_out, int out_size) {
    (void)d_in; (void)in_sizes; (void)n_in;
    if (out_size == 2048) {
        zero_out_exact<<<1, 512>>>((float4*)d_out);
    } else {
        int block = 256;
        int grid = (out_size + block - 1) / block;
        zero_out_generic<<<grid, block>>>((float*)d_out, out_size);
    }
}